// round 15
// baseline (speedup 1.0000x reference)
#include <cuda_runtime.h>

#define C 32
#define BMAX 16
#define EPS 1e-5f
#define TILE_ROWS 128

// Scratch (device globals: zero-initialized at module load; finalize_kernel
// resets them after consuming, so every graph replay starts clean).
__device__ float g_sum[BMAX * C];
__device__ float g_sq[BMAX * C];
__device__ float g_cnt[BMAX];
__device__ float g_scale[BMAX * C];
__device__ float g_shift[BMAX * C];
__device__ unsigned int g_tile_ctr;    // dynamic work counter (reduce)

// ---------------------------------------------------------------------------
// Accumulate rows [rs, re) into (s, q). Lane L covers float4-column (L&7),
// row offset (L>>3): 4 rows per LDG.128 round, 8-row loop with one-chunk
// lookahead — the R9-validated 2-deep shape (best measured: 5.1 TB/s).
// ---------------------------------------------------------------------------
__device__ __forceinline__ void acc4(const float4& v, float4& s, float4& q) {
    s.x += v.x; s.y += v.y; s.z += v.z; s.w += v.w;
    q.x = fmaf(v.x, v.x, q.x); q.y = fmaf(v.y, v.y, q.y);
    q.z = fmaf(v.z, v.z, q.z); q.w = fmaf(v.w, v.w, q.w);
}

__device__ __forceinline__ void accum_core(const float* __restrict__ data,
                                           int rs, int re, int lane,
                                           float4& s, float4& q) {
    int rows = re - rs;
    if (rows <= 0) return;
    int sub = lane & 7;
    int rg  = lane >> 3;

    const float4* base = reinterpret_cast<const float4*>(
        data + (size_t)rs * C) + (size_t)rg * 8 + sub;

    int nch = rows >> 3;               // full 8-row chunks
    int r = nch << 3;
    if (nch > 0) {
        float4 a = base[0];
        float4 c = base[32];
        for (int k = 1; k < nch; ++k) {
            const float4* p = base + (size_t)k * 64;
            float4 a2 = p[0];          // prefetch chunk k
            float4 c2 = p[32];
            acc4(a, s, q); acc4(c, s, q);
            a = a2; c = c2;
        }
        acc4(a, s, q); acc4(c, s, q);
    }
    if (r + 4 <= rows) {
        float4 a = base[(size_t)r * 8];
        acc4(a, s, q);
        r += 4;
    }
    if (r < rows && r + rg < rows) {   // 1-3 remaining rows, predicated
        float4 a = base[(size_t)r * 8];
        acc4(a, s, q);
    }
}

// Cross-lane combine + atomic flush of accumulated stats for segment b.
__device__ __forceinline__ void flush_stats(float4 s, float4 q, float cnt,
                                            int b, int lane) {
    int sub = lane & 7;
    int rg  = lane >> 3;
    #pragma unroll
    for (int off = 16; off >= 8; off >>= 1) {
        s.x += __shfl_xor_sync(0xffffffffu, s.x, off);
        s.y += __shfl_xor_sync(0xffffffffu, s.y, off);
        s.z += __shfl_xor_sync(0xffffffffu, s.z, off);
        s.w += __shfl_xor_sync(0xffffffffu, s.w, off);
        q.x += __shfl_xor_sync(0xffffffffu, q.x, off);
        q.y += __shfl_xor_sync(0xffffffffu, q.y, off);
        q.z += __shfl_xor_sync(0xffffffffu, q.z, off);
        q.w += __shfl_xor_sync(0xffffffffu, q.w, off);
    }
    if (rg == 0) {
        int b4 = b * C + sub * 4;
        atomicAdd(&g_sum[b4 + 0], s.x);
        atomicAdd(&g_sum[b4 + 1], s.y);
        atomicAdd(&g_sum[b4 + 2], s.z);
        atomicAdd(&g_sum[b4 + 3], s.w);
        atomicAdd(&g_sq[b4 + 0], q.x);
        atomicAdd(&g_sq[b4 + 1], q.y);
        atomicAdd(&g_sq[b4 + 2], q.z);
        atomicAdd(&g_sq[b4 + 3], q.w);
    }
    if (lane == 0) atomicAdd(&g_cnt[b], cnt);
}

// ---------------------------------------------------------------------------
// Kernel 1: per-segment sum / sumsq / count with DYNAMIC tile scheduling.
// Warps grab 128-row tiles from a global counter: fast SMs take more tiles,
// so the cross-CTA L1tex spread tail (the measured binder across R9-R14)
// collapses from spr*T_CTA to ~one tile. Stats are accumulated across
// tiles in registers and flushed only when the segment id changes.
// ---------------------------------------------------------------------------
__global__ void reduce_kernel(const float* __restrict__ data,
                              const int* __restrict__ bid, int N) {
    int lane = threadIdx.x & 31;
    int ntiles = (N + TILE_ROWS - 1) / TILE_ROWS;

    float4 s = make_float4(0.f, 0.f, 0.f, 0.f);
    float4 q = make_float4(0.f, 0.f, 0.f, 0.f);
    float cnt = 0.0f;
    int cur_b = -1;

    for (;;) {
        unsigned int t = 0;
        if (lane == 0) t = atomicAdd(&g_tile_ctr, 1u);
        t = __shfl_sync(0xffffffffu, t, 0);
        if (t >= (unsigned int)ntiles) break;

        int rs = (int)t * TILE_ROWS;
        int re = rs + TILE_ROWS;
        if (re > N) re = N;

        int bf = bid[rs];
        int bl = bid[re - 1];

        if (bf == bl) {
            if (bf != cur_b) {
                if (cur_b >= 0) flush_stats(s, q, cnt, cur_b, lane);
                s = make_float4(0.f, 0.f, 0.f, 0.f);
                q = make_float4(0.f, 0.f, 0.f, 0.f);
                cnt = 0.0f;
                cur_b = bf;
            }
            accum_core(data, rs, re, lane, s, q);
            cnt += (float)(re - rs);
        } else {
            // Boundary tile (<=15 total): binary-search each run.
            int r = rs;
            int b = bf;
            while (r < re) {
                int lo = r + 1, hi = re;
                while (lo < hi) {                 // broadcast loads
                    int mid = (lo + hi) >> 1;
                    if (bid[mid] == b) lo = mid + 1;
                    else hi = mid;
                }
                if (b != cur_b) {
                    if (cur_b >= 0) flush_stats(s, q, cnt, cur_b, lane);
                    s = make_float4(0.f, 0.f, 0.f, 0.f);
                    q = make_float4(0.f, 0.f, 0.f, 0.f);
                    cnt = 0.0f;
                    cur_b = b;
                }
                accum_core(data, r, lo, lane, s, q);
                cnt += (float)(lo - r);
                r = lo;
                if (r < re) b = bid[r];
            }
        }
    }
    if (cur_b >= 0) flush_stats(s, q, cnt, cur_b, lane);
}

// ---------------------------------------------------------------------------
// Kernel 2: fold stats into per-(b,c) scale/shift, THEN reset accumulators
// and the tile counter so the next graph replay starts clean.
// ---------------------------------------------------------------------------
__global__ void finalize_kernel(const float* __restrict__ w,
                                const float* __restrict__ bias) {
    int i = threadIdx.x;           // 0..BMAX*C-1
    if (i >= BMAX * C) return;
    int b = i / C, c = i % C;
    float cnt = g_cnt[b];
    float norm = 1.0f / (cnt + EPS);
    float sum = g_sum[i];
    float mean = sum * norm;
    float var = (g_sq[i] - 2.0f * mean * sum + mean * mean * cnt) * norm;
    float inv_std = rsqrtf(var + EPS);
    float wc = w ? w[c] : 1.0f;
    float bc = bias ? bias[c] : 0.0f;
    float sc = inv_std * wc;
    g_scale[i] = sc;
    g_shift[i] = bc - mean * sc;
    // Consume-and-reset for the next replay.
    g_sum[i] = 0.0f;
    g_sq[i] = 0.0f;
    if (c == 0) g_cnt[b] = 0.0f;
    if (i == 0) g_tile_ctr = 0u;
}

// ---------------------------------------------------------------------------
// Normalize one single-segment run [rs, re): scale/shift in registers
// (loaded once per run), inner loop pure LDG.128 -> FMA -> STG.128 with
// one-chunk lookahead.  [R10: 6.4 TB/s effective — at ceiling, unchanged]
// ---------------------------------------------------------------------------
__device__ __forceinline__ void norm_run(const float* __restrict__ data,
                                         float* __restrict__ out,
                                         const float4* s_scale,
                                         const float4* s_shift,
                                         int rs, int re, int b, int lane) {
    int rows = re - rs;
    if (rows <= 0) return;
    int sub = lane & 7;
    int rg  = lane >> 3;

    float4 sc = s_scale[b * 8 + sub];   // once per run
    float4 sh = s_shift[b * 8 + sub];

    const float4* pi = reinterpret_cast<const float4*>(
        data + (size_t)rs * C) + (size_t)rg * 8 + sub;
    float4* po = reinterpret_cast<float4*>(
        out + (size_t)rs * C) + (size_t)rg * 8 + sub;

    int nch = rows >> 3;               // full 8-row chunks
    int r = nch << 3;
    if (nch > 0) {
        float4 a = __ldcs(pi);
        float4 c = __ldcs(pi + 32);
        for (int k = 1; k < nch; ++k) {
            const float4* p = pi + (size_t)k * 64;
            float4 a2 = __ldcs(p);         // prefetch chunk k
            float4 c2 = __ldcs(p + 32);
            float4 o0, o1;
            o0.x = fmaf(a.x, sc.x, sh.x); o0.y = fmaf(a.y, sc.y, sh.y);
            o0.z = fmaf(a.z, sc.z, sh.z); o0.w = fmaf(a.w, sc.w, sh.w);
            o1.x = fmaf(c.x, sc.x, sh.x); o1.y = fmaf(c.y, sc.y, sh.y);
            o1.z = fmaf(c.z, sc.z, sh.z); o1.w = fmaf(c.w, sc.w, sh.w);
            float4* po_k = po + (size_t)(k - 1) * 64;
            __stcs(po_k, o0);
            __stcs(po_k + 32, o1);
            a = a2; c = c2;
        }
        float4 o0, o1;
        o0.x = fmaf(a.x, sc.x, sh.x); o0.y = fmaf(a.y, sc.y, sh.y);
        o0.z = fmaf(a.z, sc.z, sh.z); o0.w = fmaf(a.w, sc.w, sh.w);
        o1.x = fmaf(c.x, sc.x, sh.x); o1.y = fmaf(c.y, sc.y, sh.y);
        o1.z = fmaf(c.z, sc.z, sh.z); o1.w = fmaf(c.w, sc.w, sh.w);
        float4* po_k = po + (size_t)(nch - 1) * 64;
        __stcs(po_k, o0);
        __stcs(po_k + 32, o1);
    }
    if (r + 4 <= rows) {
        float4 a = __ldcs(pi + (size_t)r * 8);
        float4 o;
        o.x = fmaf(a.x, sc.x, sh.x); o.y = fmaf(a.y, sc.y, sh.y);
        o.z = fmaf(a.z, sc.z, sh.z); o.w = fmaf(a.w, sc.w, sh.w);
        __stcs(po + (size_t)r * 8, o);
        r += 4;
    }
    if (r < rows && r + rg < rows) {   // 1-3 remaining rows, predicated
        float4 a = __ldcs(pi + (size_t)r * 8);
        float4 o;
        o.x = fmaf(a.x, sc.x, sh.x); o.y = fmaf(a.y, sc.y, sh.y);
        o.z = fmaf(a.z, sc.z, sh.z); o.w = fmaf(a.w, sc.w, sh.w);
        __stcs(po + (size_t)r * 8, o);
    }
}

// ---------------------------------------------------------------------------
// Kernel 3: normalize, warp-chunked (R10-validated, at LTS ceiling).
// ---------------------------------------------------------------------------
__global__ void normalize_kernel(const float* __restrict__ data,
                                 const int* __restrict__ bid,
                                 float* __restrict__ out,
                                 int N, int rows_per_warp) {
    __shared__ float4 s_scale[BMAX * C / 4];
    __shared__ float4 s_shift[BMAX * C / 4];
    for (int i = threadIdx.x; i < BMAX * C / 4; i += blockDim.x) {
        s_scale[i] = reinterpret_cast<const float4*>(g_scale)[i];
        s_shift[i] = reinterpret_cast<const float4*>(g_shift)[i];
    }
    __syncthreads();

    int warp = (int)((blockIdx.x * blockDim.x + threadIdx.x) >> 5);
    int lane = threadIdx.x & 31;

    int r0 = warp * rows_per_warp;
    if (r0 >= N) return;
    int r1 = r0 + rows_per_warp;
    if (r1 > N) r1 = N;

    int b_first = bid[r0];
    int b_last = bid[r1 - 1];

    if (b_first == b_last) {
        norm_run(data, out, s_scale, s_shift, r0, r1, b_first, lane);
    } else {
        int r = r0;
        int b = b_first;
        while (r < r1) {
            int lo = r + 1, hi = r1;
            while (lo < hi) {
                int mid = (lo + hi) >> 1;     // broadcast load
                if (bid[mid] == b) lo = mid + 1;
                else hi = mid;
            }
            norm_run(data, out, s_scale, s_shift, r, lo, b, lane);
            r = lo;
            if (r < r1) b = bid[r];
        }
    }
}

// ---------------------------------------------------------------------------
extern "C" void kernel_launch(void* const* d_in, const int* in_sizes, int n_in,
                              void* d_out, int out_size) {
    const float* data = (const float*)d_in[0];
    const int* bid = (const int*)d_in[1];
    int N = in_sizes[0] / C;

    // Locate weights/bias among the remaining inputs (size-32 fp32 arrays).
    const float* w = nullptr;
    const float* bias = nullptr;
    for (int i = 2; i < n_in; ++i) {
        if (in_sizes[i] == C) {
            if (!w) w = (const float*)d_in[i];
            else if (!bias) bias = (const float*)d_in[i];
        }
    }

    const int threads = 256;

    // Reduce: 4 CTAs/SM (natural occupancy), dynamic 128-row tiles.
    reduce_kernel<<<148 * 4, threads>>>(data, bid, N);

    finalize_kernel<<<1, BMAX * C>>>(w, bias);

    // Normalize: single wave at 8 blocks/SM (R10-validated config).
    {
        const int blocks = 148 * 8;
        int warps = blocks * (threads / 32);
        int rpw = (N + warps - 1) / warps;
        normalize_kernel<<<blocks, threads>>>(data, bid, (float*)d_out,
                                              N, rpw);
    }
}

// round 16
// speedup vs baseline: 1.3120x; 1.3120x over previous
#include <cuda_runtime.h>

#define C 32
#define BMAX 16
#define EPS 1e-5f

// Scratch (device globals: zero-initialized at module load; the LAST
// normalize block resets them, so every graph replay starts clean).
__device__ float g_sum[BMAX * C];
__device__ float g_sq[BMAX * C];
__device__ float g_cnt[BMAX];
__device__ unsigned int g_done;

// ---------------------------------------------------------------------------
// Accumulate helpers (R9-validated 2-deep streaming shape, 5.1 TB/s).
// ---------------------------------------------------------------------------
__device__ __forceinline__ void acc4(const float4& v, float4& s, float4& q) {
    s.x += v.x; s.y += v.y; s.z += v.z; s.w += v.w;
    q.x = fmaf(v.x, v.x, q.x); q.y = fmaf(v.y, v.y, q.y);
    q.z = fmaf(v.z, v.z, q.z); q.w = fmaf(v.w, v.w, q.w);
}

// Warp-cooperative accumulation of one single-segment run [rs, re).
// Lane L covers float4-column (L&7) at row offset (L>>3): 4 rows per
// LDG.128 round, 8-row loop with one-chunk lookahead.
__device__ __forceinline__ void accum_run(const float* __restrict__ data,
                                          int rs, int re, int b, int lane) {
    int rows = re - rs;
    if (rows <= 0) return;
    int sub = lane & 7;
    int rg  = lane >> 3;

    const float4* base = reinterpret_cast<const float4*>(
        data + (size_t)rs * C) + (size_t)rg * 8 + sub;

    float4 s = make_float4(0.f, 0.f, 0.f, 0.f);
    float4 q = make_float4(0.f, 0.f, 0.f, 0.f);

    int nch = rows >> 3;               // full 8-row chunks
    int r = nch << 3;
    if (nch > 0) {
        float4 a = base[0];
        float4 c = base[32];
        for (int k = 1; k < nch; ++k) {
            const float4* p = base + (size_t)k * 64;
            float4 a2 = p[0];          // prefetch chunk k
            float4 c2 = p[32];
            acc4(a, s, q); acc4(c, s, q);
            a = a2; c = c2;
        }
        acc4(a, s, q); acc4(c, s, q);
    }
    if (r + 4 <= rows) {
        float4 a = base[(size_t)r * 8];
        acc4(a, s, q);
        r += 4;
    }
    if (r < rows && r + rg < rows) {   // 1-3 remaining rows, predicated
        float4 a = base[(size_t)r * 8];
        acc4(a, s, q);
    }

    // Combine lanes sharing the same channels (rg = 0..3): xor 16, 8.
    #pragma unroll
    for (int off = 16; off >= 8; off >>= 1) {
        s.x += __shfl_xor_sync(0xffffffffu, s.x, off);
        s.y += __shfl_xor_sync(0xffffffffu, s.y, off);
        s.z += __shfl_xor_sync(0xffffffffu, s.z, off);
        s.w += __shfl_xor_sync(0xffffffffu, s.w, off);
        q.x += __shfl_xor_sync(0xffffffffu, q.x, off);
        q.y += __shfl_xor_sync(0xffffffffu, q.y, off);
        q.z += __shfl_xor_sync(0xffffffffu, q.z, off);
        q.w += __shfl_xor_sync(0xffffffffu, q.w, off);
    }

    if (rg == 0) {   // lanes 0..7 flush channels sub*4 .. sub*4+3
        int b4 = b * C + sub * 4;
        atomicAdd(&g_sum[b4 + 0], s.x);
        atomicAdd(&g_sum[b4 + 1], s.y);
        atomicAdd(&g_sum[b4 + 2], s.z);
        atomicAdd(&g_sum[b4 + 3], s.w);
        atomicAdd(&g_sq[b4 + 0], q.x);
        atomicAdd(&g_sq[b4 + 1], q.y);
        atomicAdd(&g_sq[b4 + 2], q.z);
        atomicAdd(&g_sq[b4 + 3], q.w);
    }
    if (lane == 0) atomicAdd(&g_cnt[b], (float)rows);
}

// ---------------------------------------------------------------------------
// Kernel 1: per-segment sum / sumsq / count. Static warp partition at
// oe=3 (148*3 CTAs): measured BW rises monotonically as CTA concurrency
// drops (oe 6->4: 4.1->5.1 TB/s); this probes the next point down.
// Boundary chunks (<=15 warps) binary-search their <=16 runs.
// ---------------------------------------------------------------------------
__global__ void reduce_kernel(const float* __restrict__ data,
                              const int* __restrict__ bid,
                              int N, int rows_per_warp) {
    int warp = (int)((blockIdx.x * blockDim.x + threadIdx.x) >> 5);
    int lane = threadIdx.x & 31;

    int r0 = warp * rows_per_warp;
    if (r0 >= N) return;
    int r1 = r0 + rows_per_warp;
    if (r1 > N) r1 = N;

    int b_first = bid[r0];
    int b_last = bid[r1 - 1];

    if (b_first == b_last) {
        accum_run(data, r0, r1, b_first, lane);
    } else {
        int r = r0;
        int b = b_first;
        while (r < r1) {
            int lo = r + 1, hi = r1;
            while (lo < hi) {                 // binary search run end
                int mid = (lo + hi) >> 1;     // broadcast load
                if (bid[mid] == b) lo = mid + 1;
                else hi = mid;
            }
            accum_run(data, r, lo, b, lane);
            r = lo;
            if (r < r1) b = bid[r];
        }
    }
}

// ---------------------------------------------------------------------------
// Normalize one single-segment run [rs, re): scale/shift in registers
// (loaded once per run), inner loop pure LDG.128 -> FMA -> STG.128 with
// one-chunk lookahead.  [R10: 5.8 TB/s DRAM — at ceiling, unchanged]
// ---------------------------------------------------------------------------
__device__ __forceinline__ void norm_run(const float* __restrict__ data,
                                         float* __restrict__ out,
                                         const float4* s_scale,
                                         const float4* s_shift,
                                         int rs, int re, int b, int lane) {
    int rows = re - rs;
    if (rows <= 0) return;
    int sub = lane & 7;
    int rg  = lane >> 3;

    float4 sc = s_scale[b * 8 + sub];   // once per run
    float4 sh = s_shift[b * 8 + sub];

    const float4* pi = reinterpret_cast<const float4*>(
        data + (size_t)rs * C) + (size_t)rg * 8 + sub;
    float4* po = reinterpret_cast<float4*>(
        out + (size_t)rs * C) + (size_t)rg * 8 + sub;

    int nch = rows >> 3;               // full 8-row chunks
    int r = nch << 3;
    if (nch > 0) {
        float4 a = __ldcs(pi);
        float4 c = __ldcs(pi + 32);
        for (int k = 1; k < nch; ++k) {
            const float4* p = pi + (size_t)k * 64;
            float4 a2 = __ldcs(p);         // prefetch chunk k
            float4 c2 = __ldcs(p + 32);
            float4 o0, o1;
            o0.x = fmaf(a.x, sc.x, sh.x); o0.y = fmaf(a.y, sc.y, sh.y);
            o0.z = fmaf(a.z, sc.z, sh.z); o0.w = fmaf(a.w, sc.w, sh.w);
            o1.x = fmaf(c.x, sc.x, sh.x); o1.y = fmaf(c.y, sc.y, sh.y);
            o1.z = fmaf(c.z, sc.z, sh.z); o1.w = fmaf(c.w, sc.w, sh.w);
            float4* po_k = po + (size_t)(k - 1) * 64;
            __stcs(po_k, o0);
            __stcs(po_k + 32, o1);
            a = a2; c = c2;
        }
        float4 o0, o1;
        o0.x = fmaf(a.x, sc.x, sh.x); o0.y = fmaf(a.y, sc.y, sh.y);
        o0.z = fmaf(a.z, sc.z, sh.z); o0.w = fmaf(a.w, sc.w, sh.w);
        o1.x = fmaf(c.x, sc.x, sh.x); o1.y = fmaf(c.y, sc.y, sh.y);
        o1.z = fmaf(c.z, sc.z, sh.z); o1.w = fmaf(c.w, sc.w, sh.w);
        float4* po_k = po + (size_t)(nch - 1) * 64;
        __stcs(po_k, o0);
        __stcs(po_k + 32, o1);
    }
    if (r + 4 <= rows) {
        float4 a = __ldcs(pi + (size_t)r * 8);
        float4 o;
        o.x = fmaf(a.x, sc.x, sh.x); o.y = fmaf(a.y, sc.y, sh.y);
        o.z = fmaf(a.z, sc.z, sh.z); o.w = fmaf(a.w, sc.w, sh.w);
        __stcs(po + (size_t)r * 8, o);
        r += 4;
    }
    if (r < rows && r + rg < rows) {   // 1-3 remaining rows, predicated
        float4 a = __ldcs(pi + (size_t)r * 8);
        float4 o;
        o.x = fmaf(a.x, sc.x, sh.x); o.y = fmaf(a.y, sc.y, sh.y);
        o.z = fmaf(a.z, sc.z, sh.z); o.w = fmaf(a.w, sc.w, sh.w);
        __stcs(po + (size_t)r * 8, o);
    }
}

// ---------------------------------------------------------------------------
// Kernel 2: normalize + folded finalize.
// Each block derives the 512 scale/shift values from the raw accumulators
// (2 elems/thread, L2-broadcast reads) — no separate finalize launch.
// The LAST block to finish (completion counter) resets the accumulators
// for the next graph replay; every block increments only AFTER its own
// reads, so the reset never races a reader. No early returns before
// __syncthreads (work is guarded instead).
// ---------------------------------------------------------------------------
__global__ void normalize_kernel(const float* __restrict__ data,
                                 const int* __restrict__ bid,
                                 const float* __restrict__ w,
                                 const float* __restrict__ bias,
                                 float* __restrict__ out,
                                 int N, int rows_per_warp) {
    __shared__ __align__(16) float sm_scale[BMAX * C];
    __shared__ __align__(16) float sm_shift[BMAX * C];
    __shared__ int sm_last;

    // Folded finalize: compute scale/shift from raw stats.
    for (int i = threadIdx.x; i < BMAX * C; i += blockDim.x) {
        int b = i >> 5, c = i & 31;
        float cnt = g_cnt[b];
        float norm = 1.0f / (cnt + EPS);
        float sum = g_sum[i];
        float mean = sum * norm;
        float var = (g_sq[i] - 2.0f * mean * sum + mean * mean * cnt) * norm;
        float inv_std = rsqrtf(var + EPS);
        float wc = w ? w[c] : 1.0f;
        float bc = bias ? bias[c] : 0.0f;
        float sc = inv_std * wc;
        sm_scale[i] = sc;
        sm_shift[i] = bc - mean * sc;
    }
    __syncthreads();

    const float4* s_scale = reinterpret_cast<const float4*>(sm_scale);
    const float4* s_shift = reinterpret_cast<const float4*>(sm_shift);

    int warp = (int)((blockIdx.x * blockDim.x + threadIdx.x) >> 5);
    int lane = threadIdx.x & 31;

    int r0 = warp * rows_per_warp;
    if (r0 < N) {
        int r1 = r0 + rows_per_warp;
        if (r1 > N) r1 = N;

        int b_first = bid[r0];
        int b_last = bid[r1 - 1];

        if (b_first == b_last) {
            norm_run(data, out, s_scale, s_shift, r0, r1, b_first, lane);
        } else {
            int r = r0;
            int b = b_first;
            while (r < r1) {
                int lo = r + 1, hi = r1;
                while (lo < hi) {
                    int mid = (lo + hi) >> 1;     // broadcast load
                    if (bid[mid] == b) lo = mid + 1;
                    else hi = mid;
                }
                norm_run(data, out, s_scale, s_shift, r, lo, b, lane);
                r = lo;
                if (r < r1) b = bid[r];
            }
        }
    }

    // Consume-and-reset: last finishing block zeroes the accumulators.
    __syncthreads();
    if (threadIdx.x == 0) {
        unsigned int old = atomicAdd(&g_done, 1u);
        sm_last = (old == gridDim.x - 1) ? 1 : 0;
    }
    __syncthreads();
    if (sm_last) {
        for (int i = threadIdx.x; i < BMAX * C; i += blockDim.x) {
            g_sum[i] = 0.0f;
            g_sq[i] = 0.0f;
        }
        if (threadIdx.x < BMAX) g_cnt[threadIdx.x] = 0.0f;
        if (threadIdx.x == 0) g_done = 0u;
    }
}

// ---------------------------------------------------------------------------
extern "C" void kernel_launch(void* const* d_in, const int* in_sizes, int n_in,
                              void* d_out, int out_size) {
    const float* data = (const float*)d_in[0];
    const int* bid = (const int*)d_in[1];
    int N = in_sizes[0] / C;

    // Locate weights/bias among the remaining inputs (size-32 fp32 arrays).
    const float* w = nullptr;
    const float* bias = nullptr;
    for (int i = 2; i < n_in; ++i) {
        if (in_sizes[i] == C) {
            if (!w) w = (const float*)d_in[i];
            else if (!bias) bias = (const float*)d_in[i];
        }
    }

    const int threads = 256;

    // Reduce: single wave at 3 CTAs/SM (oe=3 probe).
    {
        const int blocks = 148 * 3;
        int warps = blocks * (threads / 32);
        int rpw = (N + warps - 1) / warps;
        reduce_kernel<<<blocks, threads>>>(data, bid, N, rpw);
    }

    // Normalize (+ folded finalize): single wave at 8 blocks/SM.
    {
        const int blocks = 148 * 8;
        int warps = blocks * (threads / 32);
        int rpw = (N + warps - 1) / warps;
        normalize_kernel<<<blocks, threads>>>(data, bid, w, bias,
                                              (float*)d_out, N, rpw);
    }
}